// round 1
// baseline (speedup 1.0000x reference)
#include <cuda_runtime.h>
#include <math.h>

#define D    256
#define S    32
#define CTX  33
#define MAXN 20000

// ---- scratch (device globals; no allocation allowed) ----
__device__ float g_A[D * D];        // Wq^T Wk
__device__ float g_q[D];            // Wk^T bq
__device__ float g_WvT[D * D];      // Wv transposed: WvT[f*D+d] = Wv[d*D+f]
__device__ float g_Qt[MAXN * D];    // per-node query in context space
__device__ float g_ctxmix[MAXN * D];// attention-weighted context features

// ============================================================
// prep: A = Wq^T Wk, q = Wk^T bq, WvT = Wv^T
// grid = 2*D + 1 blocks, 256 threads
// ============================================================
__global__ void prep_kernel(const float* __restrict__ Wq,
                            const float* __restrict__ bq,
                            const float* __restrict__ Wk,
                            const float* __restrict__ Wv)
{
    __shared__ float sv[D];
    int b = blockIdx.x;
    int t = threadIdx.x;

    if (b < D) {
        // A[b][f] = sum_d Wq[d][b] * Wk[d][f]
        sv[t] = Wq[t * D + b];
        __syncthreads();
        float acc = 0.f;
        #pragma unroll 8
        for (int d = 0; d < D; d++) acc += sv[d] * Wk[d * D + t];
        g_A[b * D + t] = acc;
    } else if (b == D) {
        // q[f] = sum_d bq[d] * Wk[d][f]
        sv[t] = bq[t];
        __syncthreads();
        float acc = 0.f;
        #pragma unroll 8
        for (int d = 0; d < D; d++) acc += sv[d] * Wk[d * D + t];
        g_q[t] = acc;
    } else {
        // transpose Wv
        int dd = b - (D + 1);
        g_WvT[t * D + dd] = Wv[dd * D + t];
    }
}

// ============================================================
// GEMM: out[M,256] = X[M,256] @ W[256,256] + bias  (+ optional tanh)
// MODE 0: X = gather(feat_table, node_ids), W = g_A,  bias = g_q,  out = g_Qt
// MODE 1: X = g_ctxmix,                     W = g_WvT, bias = bv, out = d_out (tanh)
// Block tile: 64 rows x 256 cols, BK=32. 256 threads, 8x8 micro-tile/thread.
// ============================================================
template <int MODE>
__global__ __launch_bounds__(256)
void gemm_kernel(const int* __restrict__ gidx,
                 const float* __restrict__ table,
                 const float* __restrict__ bias_in,
                 float* __restrict__ out_p,
                 int M)
{
    __shared__ float sX[64][36];     // padded to avoid store conflicts
    __shared__ float sW[32 * 256];

    const int tid = threadIdx.x;
    const int tx  = tid & 31;        // 0..31 -> col group
    const int ty  = tid >> 5;        // 0..7  -> row group
    const int m0  = blockIdx.x * 64;

    // X-tile load assignment: thread -> (row lr, col-chunk lc)
    const int lr = tid >> 2;          // 0..63
    const int lc = (tid & 3) * 8;     // 0,8,16,24

    int m  = m0 + lr;
    int mm = (m < M) ? m : (M - 1);
    const float* rowp;
    if (MODE == 0) rowp = table + (size_t)gidx[mm] * D;
    else           rowp = g_ctxmix + (size_t)mm * D;

    const float* Wm = (MODE == 0) ? g_A : g_WvT;

    float acc[8][8];
    #pragma unroll
    for (int i = 0; i < 8; i++)
        #pragma unroll
        for (int j = 0; j < 8; j++) acc[i][j] = 0.f;

    for (int kt = 0; kt < D; kt += 32) {
        // load X tile (64x32)
        float4 a0 = *(const float4*)(rowp + kt + lc);
        float4 a1 = *(const float4*)(rowp + kt + lc + 4);
        *(float4*)(&sX[lr][lc])     = a0;
        *(float4*)(&sX[lr][lc + 4]) = a1;
        // load W tile (32x256 contiguous)
        const float* wp = Wm + kt * D;
        #pragma unroll
        for (int i = 0; i < 8; i++) {
            *(float4*)(&sW[tid * 4 + i * 1024]) =
                *(const float4*)(wp + tid * 4 + i * 1024);
        }
        __syncthreads();

        #pragma unroll
        for (int kk = 0; kk < 32; kk++) {
            float xf[8];
            #pragma unroll
            for (int i = 0; i < 8; i++) xf[i] = sX[ty * 8 + i][kk];
            float4 w0 = *(const float4*)(&sW[kk * 256 + tx * 8]);
            float4 w1 = *(const float4*)(&sW[kk * 256 + tx * 8 + 4]);
            float wf[8] = {w0.x, w0.y, w0.z, w0.w, w1.x, w1.y, w1.z, w1.w};
            #pragma unroll
            for (int i = 0; i < 8; i++)
                #pragma unroll
                for (int j = 0; j < 8; j++)
                    acc[i][j] += xf[i] * wf[j];
        }
        __syncthreads();
    }

    const float* bias = (MODE == 0) ? g_q : bias_in;
    float4 b0 = *(const float4*)(bias + tx * 8);
    float4 b1 = *(const float4*)(bias + tx * 8 + 4);
    float bz[8] = {b0.x, b0.y, b0.z, b0.w, b1.x, b1.y, b1.z, b1.w};

    float* out = (MODE == 0) ? g_Qt : out_p;

    #pragma unroll
    for (int i = 0; i < 8; i++) {
        int mrow = m0 + ty * 8 + i;
        if (mrow < M) {
            float v[8];
            #pragma unroll
            for (int j = 0; j < 8; j++) {
                float x = acc[i][j] + bz[j];
                v[j] = (MODE == 1) ? tanhf(x) : x;
            }
            float4 o0 = {v[0], v[1], v[2], v[3]};
            float4 o1 = {v[4], v[5], v[6], v[7]};
            *(float4*)(out + (size_t)mrow * D + tx * 8)     = o0;
            *(float4*)(out + (size_t)mrow * D + tx * 8 + 4) = o1;
        }
    }
}

// ============================================================
// attention: per node, gather 33 ctx rows once into SMEM,
// scores = Qt . ctx, softmax(33), ctxmix = sum attn_k * ctx_k
// grid = N blocks, 256 threads (8 warps)
// ============================================================
__global__ __launch_bounds__(256)
void attn_kernel(const int* __restrict__ node_ids,
                 const int* __restrict__ neigh_ids,
                 const float* __restrict__ table)
{
    __shared__ float sCtx[CTX * D];
    __shared__ float sScore[CTX];

    const int n    = blockIdx.x;
    const int tid  = threadIdx.x;
    const int warp = tid >> 5;
    const int lane = tid & 31;

    // Qt fragment: lane owns floats [lane*4 .. +3] and [128+lane*4 .. +3]
    const float* qtp = g_Qt + (size_t)n * D;
    float4 q0 = *(const float4*)(qtp + lane * 4);
    float4 q1 = *(const float4*)(qtp + 128 + lane * 4);

    // pass 1: each warp gathers rows k = warp, warp+8, ... and computes dots
    for (int k = warp; k < CTX; k += 8) {
        int id = (k == 0) ? node_ids[n] : neigh_ids[(size_t)n * S + (k - 1)];
        const float4* row = (const float4*)(table + (size_t)id * D);
        float4 a = row[lane];
        float4 b = row[32 + lane];
        *(float4*)(&sCtx[k * D + lane * 4])       = a;
        *(float4*)(&sCtx[k * D + 128 + lane * 4]) = b;
        float d = a.x * q0.x + a.y * q0.y + a.z * q0.z + a.w * q0.w
                + b.x * q1.x + b.y * q1.y + b.z * q1.z + b.w * q1.w;
        #pragma unroll
        for (int off = 16; off > 0; off >>= 1)
            d += __shfl_xor_sync(0xFFFFFFFFu, d, off);
        if (lane == 0) sScore[k] = d;
    }
    __syncthreads();

    // softmax over 33 scores (warp 0)
    if (warp == 0) {
        float s0 = sScore[lane];
        float s1 = (lane == 0) ? sScore[32] : -3.4e38f;
        float mx = fmaxf(s0, s1);
        #pragma unroll
        for (int off = 16; off > 0; off >>= 1)
            mx = fmaxf(mx, __shfl_xor_sync(0xFFFFFFFFu, mx, off));
        float e0 = expf(s0 - mx);
        float e1 = (lane == 0) ? expf(s1 - mx) : 0.f;
        float sum = e0 + e1;
        #pragma unroll
        for (int off = 16; off > 0; off >>= 1)
            sum += __shfl_xor_sync(0xFFFFFFFFu, sum, off);
        float inv = 1.f / sum;
        sScore[lane] = e0 * inv;
        if (lane == 0) sScore[32] = e1 * inv;
    }
    __syncthreads();

    // pass 2: thread tid owns feature dim f = tid
    float accv = 0.f;
    #pragma unroll
    for (int k = 0; k < CTX; k++)
        accv += sScore[k] * sCtx[k * D + tid];
    g_ctxmix[(size_t)n * D + tid] = accv;
}

// ============================================================
// L2 normalize rows of d_out in place (eps clamp = 1e-12)
// ============================================================
__global__ __launch_bounds__(256)
void norm_kernel(float* __restrict__ out)
{
    __shared__ float ws[8];
    __shared__ float snorm;
    const int n    = blockIdx.x;
    const int tid  = threadIdx.x;
    const int warp = tid >> 5;
    const int lane = tid & 31;

    float v = out[(size_t)n * D + tid];
    float s = v * v;
    #pragma unroll
    for (int off = 16; off > 0; off >>= 1)
        s += __shfl_xor_sync(0xFFFFFFFFu, s, off);
    if (lane == 0) ws[warp] = s;
    __syncthreads();
    if (tid == 0) {
        float t = 0.f;
        #pragma unroll
        for (int i = 0; i < 8; i++) t += ws[i];
        snorm = fmaxf(sqrtf(t), 1e-12f);
    }
    __syncthreads();
    out[(size_t)n * D + tid] = v / snorm;
}

// ============================================================
// launch
// inputs: node_ids, neigh_ids, feat_table, Wq, bq, Wk, bk, Wv, bv
// (bk unused: it only enters softmax-invariant terms)
// ============================================================
extern "C" void kernel_launch(void* const* d_in, const int* in_sizes, int n_in,
                              void* d_out, int out_size)
{
    const int*   node_ids  = (const int*)d_in[0];
    const int*   neigh_ids = (const int*)d_in[1];
    const float* feat      = (const float*)d_in[2];
    const float* Wq        = (const float*)d_in[3];
    const float* bq        = (const float*)d_in[4];
    const float* Wk        = (const float*)d_in[5];
    // d_in[6] = bk (provably unused after softmax-invariance elimination)
    const float* Wv        = (const float*)d_in[7];
    const float* bv        = (const float*)d_in[8];
    float*       out       = (float*)d_out;

    int N = in_sizes[0];
    if (N > MAXN) N = MAXN;

    int gemm_blocks = (N + 63) / 64;

    prep_kernel<<<2 * D + 1, 256>>>(Wq, bq, Wk, Wv);
    gemm_kernel<0><<<gemm_blocks, 256>>>(node_ids, feat, nullptr, nullptr, N);
    attn_kernel<<<N, 256>>>(node_ids, neigh_ids, feat);
    gemm_kernel<1><<<gemm_blocks, 256>>>(nullptr, nullptr, bv, out, N);
    norm_kernel<<<N, 256>>>(out);
}

// round 3
// speedup vs baseline: 1.1352x; 1.1352x over previous
#include <cuda_runtime.h>
#include <math.h>

#define D    256
#define S    32
#define CTX  33
#define MAXN 20000

typedef unsigned long long ull;

// ---- scratch (device globals; 16B-aligned for float4 access) ----
__device__ __align__(16) float g_A[D * D];        // Wq^T Wk
__device__ __align__(16) float g_q[D];            // Wk^T bq
__device__ __align__(16) float g_WvT[D * D];      // Wv transposed
__device__ __align__(16) float g_Qt[MAXN * D];    // per-node query in ctx space
__device__ __align__(16) float g_ctxmix[MAXN * D];// attn-weighted context

// ---- packed f32x2 helpers ----
__device__ __forceinline__ ull bcast2(float x) {
    ull r;
    asm("mov.b64 %0, {%1, %1};" : "=l"(r) : "f"(x));
    return r;
}
__device__ __forceinline__ float2 unpk2(ull v) {
    float2 f;
    asm("mov.b64 {%0, %1}, %2;" : "=f"(f.x), "=f"(f.y) : "l"(v));
    return f;
}
__device__ __forceinline__ void ffma2(ull& d, ull a, ull b) {
    asm("fma.rn.f32x2 %0, %1, %2, %0;" : "+l"(d) : "l"(a), "l"(b));
}

// ============================================================
// prep: A = Wq^T Wk, q = Wk^T bq, WvT = Wv^T
// ============================================================
__global__ void prep_kernel(const float* __restrict__ Wq,
                            const float* __restrict__ bq,
                            const float* __restrict__ Wk,
                            const float* __restrict__ Wv)
{
    __shared__ __align__(16) float sv[D];
    int b = blockIdx.x;
    int t = threadIdx.x;

    if (b < D) {
        sv[t] = Wq[t * D + b];
        __syncthreads();
        float acc = 0.f;
        #pragma unroll 8
        for (int d = 0; d < D; d++) acc += sv[d] * Wk[d * D + t];
        g_A[b * D + t] = acc;
    } else if (b == D) {
        sv[t] = bq[t];
        __syncthreads();
        float acc = 0.f;
        #pragma unroll 8
        for (int d = 0; d < D; d++) acc += sv[d] * Wk[d * D + t];
        g_q[t] = acc;
    } else {
        int dd = b - (D + 1);
        g_WvT[t * D + dd] = Wv[dd * D + t];
    }
}

// ============================================================
// GEMM: out[M,256] = X[M,256] @ W[256,256] + bias
// MODE 0: X = gather(table, idx), W = g_A,  bias = g_q, out = g_Qt
// MODE 1: X = g_ctxmix, W = g_WvT, bias = bv, out = d_out, tanh + L2-norm
// 64x256 block tile, BK=32, 256 threads, 8x8 micro-tile via f32x2.
// ============================================================
template <int MODE>
__global__ __launch_bounds__(256)
void gemm_kernel(const int* __restrict__ gidx,
                 const float* __restrict__ table,
                 const float* __restrict__ bias_in,
                 float* __restrict__ out_p,
                 int M)
{
    __shared__ __align__(16) float sX[64][36];
    __shared__ __align__(16) float sW[32 * 256];

    const int tid = threadIdx.x;
    const int tx  = tid & 31;
    const int ty  = tid >> 5;
    const int m0  = blockIdx.x * 64;

    const int lr = tid >> 2;
    const int lc = (tid & 3) * 8;

    int m  = m0 + lr;
    int mm = (m < M) ? m : (M - 1);
    const float* rowp;
    if (MODE == 0) rowp = table + (size_t)gidx[mm] * D;
    else           rowp = g_ctxmix + (size_t)mm * D;

    const float* Wm = (MODE == 0) ? g_A : g_WvT;

    ull acc2[8][4];
    #pragma unroll
    for (int i = 0; i < 8; i++)
        #pragma unroll
        for (int j = 0; j < 4; j++) acc2[i][j] = 0ULL;

    for (int kt = 0; kt < D; kt += 32) {
        float4 a0 = *(const float4*)(rowp + kt + lc);
        float4 a1 = *(const float4*)(rowp + kt + lc + 4);
        *(float4*)(&sX[lr][lc])     = a0;
        *(float4*)(&sX[lr][lc + 4]) = a1;
        const float* wp = Wm + kt * D;
        #pragma unroll
        for (int i = 0; i < 8; i++) {
            *(float4*)(&sW[tid * 4 + i * 1024]) =
                *(const float4*)(wp + tid * 4 + i * 1024);
        }
        __syncthreads();

        const ull* sW64 = (const ull*)sW;
        #pragma unroll
        for (int kk = 0; kk < 32; kk++) {
            ull xb[8];
            #pragma unroll
            for (int i = 0; i < 8; i++) xb[i] = bcast2(sX[ty * 8 + i][kk]);
            // 32 bytes of W for this thread: 4 packed pairs (16B-aligned)
            ulonglong2 wv0 = *(const ulonglong2*)(&sW64[kk * 128 + tx * 4]);
            ulonglong2 wv1 = *(const ulonglong2*)(&sW64[kk * 128 + tx * 4 + 2]);
            ull wp2[4] = {wv0.x, wv0.y, wv1.x, wv1.y};
            #pragma unroll
            for (int i = 0; i < 8; i++)
                #pragma unroll
                for (int j = 0; j < 4; j++)
                    ffma2(acc2[i][j], xb[i], wp2[j]);
        }
        __syncthreads();
    }

    const float* bias = (MODE == 0) ? g_q : bias_in;
    float4 b0 = *(const float4*)(bias + tx * 8);
    float4 b1 = *(const float4*)(bias + tx * 8 + 4);
    float bz[8] = {b0.x, b0.y, b0.z, b0.w, b1.x, b1.y, b1.z, b1.w};

    float* out = (MODE == 0) ? g_Qt : out_p;

    #pragma unroll
    for (int i = 0; i < 8; i++) {
        int mrow = m0 + ty * 8 + i;
        float v[8];
        #pragma unroll
        for (int j = 0; j < 4; j++) {
            float2 f = unpk2(acc2[i][j]);
            v[2 * j]     = f.x + bz[2 * j];
            v[2 * j + 1] = f.y + bz[2 * j + 1];
        }
        if (MODE == 1) {
            // tanh + row-wise L2 normalize (warp ty owns the full row)
            float s = 0.f;
            #pragma unroll
            for (int j = 0; j < 8; j++) {
                v[j] = tanhf(v[j]);
                s += v[j] * v[j];
            }
            #pragma unroll
            for (int off = 16; off > 0; off >>= 1)
                s += __shfl_xor_sync(0xFFFFFFFFu, s, off);
            float inv = 1.f / fmaxf(sqrtf(s), 1e-12f);
            #pragma unroll
            for (int j = 0; j < 8; j++) v[j] *= inv;
        }
        if (mrow < M) {
            float4 o0 = {v[0], v[1], v[2], v[3]};
            float4 o1 = {v[4], v[5], v[6], v[7]};
            *(float4*)(out + (size_t)mrow * D + tx * 8)     = o0;
            *(float4*)(out + (size_t)mrow * D + tx * 8 + 4) = o1;
        }
    }
}

// ============================================================
// attention: register-resident ctx rows.
// Warp w owns rows k = w + 8r (warp 0 also owns k=32).
// ============================================================
__global__ __launch_bounds__(256)
void attn_kernel(const int* __restrict__ node_ids,
                 const int* __restrict__ neigh_ids,
                 const float* __restrict__ table)
{
    __shared__ __align__(16) float sScore[CTX + 3];
    __shared__ __align__(16) float sPart[8][256];

    const int n    = blockIdx.x;
    const int tid  = threadIdx.x;
    const int warp = tid >> 5;
    const int lane = tid & 31;

    const float* qtp = g_Qt + (size_t)n * D;
    float4 q0 = *(const float4*)(qtp + lane * 4);
    float4 q1 = *(const float4*)(qtp + 128 + lane * 4);

    float4 ra[5], rb[5];
    const int nrows = (warp == 0) ? 5 : 4;

    #pragma unroll
    for (int r = 0; r < 5; r++) {
        if (r < nrows) {
            int k  = warp + r * 8;
            int id = (k == 0) ? node_ids[n]
                              : neigh_ids[(size_t)n * S + (k - 1)];
            const float4* row = (const float4*)(table + (size_t)id * D);
            ra[r] = row[lane];
            rb[r] = row[32 + lane];
            float d = ra[r].x * q0.x + ra[r].y * q0.y + ra[r].z * q0.z + ra[r].w * q0.w
                    + rb[r].x * q1.x + rb[r].y * q1.y + rb[r].z * q1.z + rb[r].w * q1.w;
            #pragma unroll
            for (int off = 16; off > 0; off >>= 1)
                d += __shfl_xor_sync(0xFFFFFFFFu, d, off);
            if (lane == 0) sScore[k] = d;
        }
    }
    __syncthreads();

    if (warp == 0) {
        float s0 = sScore[lane];
        float s1 = (lane == 0) ? sScore[32] : -3.4e38f;
        float mx = fmaxf(s0, s1);
        #pragma unroll
        for (int off = 16; off > 0; off >>= 1)
            mx = fmaxf(mx, __shfl_xor_sync(0xFFFFFFFFu, mx, off));
        float e0 = expf(s0 - mx);
        float e1 = (lane == 0) ? expf(s1 - mx) : 0.f;
        float sum = e0 + e1;
        #pragma unroll
        for (int off = 16; off > 0; off >>= 1)
            sum += __shfl_xor_sync(0xFFFFFFFFu, sum, off);
        float inv = 1.f / sum;
        sScore[lane] = e0 * inv;
        if (lane == 0) sScore[32] = e1 * inv;
    }
    __syncthreads();

    float4 pa = {0.f, 0.f, 0.f, 0.f};
    float4 pb = {0.f, 0.f, 0.f, 0.f};
    #pragma unroll
    for (int r = 0; r < 5; r++) {
        if (r < nrows) {
            float w = sScore[warp + r * 8];
            pa.x += w * ra[r].x; pa.y += w * ra[r].y;
            pa.z += w * ra[r].z; pa.w += w * ra[r].w;
            pb.x += w * rb[r].x; pb.y += w * rb[r].y;
            pb.z += w * rb[r].z; pb.w += w * rb[r].w;
        }
    }
    *(float4*)(&sPart[warp][lane * 4])       = pa;
    *(float4*)(&sPart[warp][128 + lane * 4]) = pb;
    __syncthreads();

    float acc = 0.f;
    #pragma unroll
    for (int w = 0; w < 8; w++) acc += sPart[w][tid];
    g_ctxmix[(size_t)n * D + tid] = acc;
}

// ============================================================
// launch:  node_ids, neigh_ids, feat_table, Wq, bq, Wk, bk, Wv, bv
// (bk only enters softmax-invariant terms -> provably unused)
// ============================================================
extern "C" void kernel_launch(void* const* d_in, const int* in_sizes, int n_in,
                              void* d_out, int out_size)
{
    const int*   node_ids  = (const int*)d_in[0];
    const int*   neigh_ids = (const int*)d_in[1];
    const float* feat      = (const float*)d_in[2];
    const float* Wq        = (const float*)d_in[3];
    const float* bq        = (const float*)d_in[4];
    const float* Wk        = (const float*)d_in[5];
    const float* Wv        = (const float*)d_in[7];
    const float* bv        = (const float*)d_in[8];
    float*       out       = (float*)d_out;

    int N = in_sizes[0];
    if (N > MAXN) N = MAXN;

    int gemm_blocks = (N + 63) / 64;

    prep_kernel<<<2 * D + 1, 256>>>(Wq, bq, Wk, Wv);
    gemm_kernel<0><<<gemm_blocks, 256>>>(node_ids, feat, nullptr, nullptr, N);
    attn_kernel<<<N, 256>>>(node_ids, neigh_ids, feat);
    gemm_kernel<1><<<gemm_blocks, 256>>>(nullptr, nullptr, bv, out, N);
}